// round 15
// baseline (speedup 1.0000x reference)
#include <cuda_runtime.h>
#include <cstddef>

// UpsampleUpFIRDn: x (8,64,256,256) f32 -> out (8,64,512,512) f32, up=2, 4x4 FIR.
// Separable parity-reduced form (verified R1/R3):
//   per input row, window (v0=x[n-1], v1=x[n], v2=x[n+1]):
//     hE = g1*v1 + g3*v0 ; hO = g2*v1 + g0*v2      (g_j = k[0][j])
//   vertical combine rows a=m-1, b=m, c=m+1 (r_i = k[i][0]/k[0][0], r0=1):
//     out[2m  ][2n] = r1*bhE + r3*ahE   out[2m  ][2n+1] = r1*bhO + r3*ahO
//     out[2m+1][2n] = r2*bhE + chE      out[2m+1][2n+1] = r2*bhO + chO
//
// FINAL. Full-width 34x264 smem slab per block, thread = 1 col x 32 rolling
// rows, stride-1 lane mapping (conflict-free LDS), STG.64 write-back stores,
// FIR weights read in-kernel (single graph node).
//
// Closed at the HBM wall: traffic = compulsory minimum (~611 MB/replay =
// 512 MB mandatory write + ~99 MB read, input partially L2-resident across
// graph replays), achieved 6.1-6.2 TB/s. The B300 LTS cap is path-
// independent (LDG.cv == TMA), so no access-path rewrite can exceed this
// drain rate. Identical-binary noise: 102.69/102.88/102.91/103.17/104.96 us.
// Rejected by experiment: per-thread register blocking (spills, -42%),
// barrier-free streaming (-11%), STG.128 2-col threads (-4%, LDS bank
// conflicts), __stcs, L2 evict_last/evict_first steering, 256-bit loads,
// tile-shape and occupancy sweeps 35-93% (all within noise).

#define IH 256
#define IW 256
#define OW 512

#define TILE_Y 32
#define SM_ROWS 34          // TILE_Y + 2 row halo
#define SM_STRIDE 264       // 4 pad | 256 | 4 pad  (col c <-> global col c-4)

__global__ __launch_bounds__(256)
void upfirdn2x_kernel(const float* __restrict__ x,
                      const float* __restrict__ kk,
                      float* __restrict__ out)
{
    __shared__ float s[SM_ROWS][SM_STRIDE];

    const int tid = threadIdx.x;
    const int m0  = blockIdx.x * TILE_Y;    // input row origin
    const int p   = blockIdx.y;             // plane (N*C)

    const float* xp = x + (size_t)p * (IH * IW);
    float* op = out + (size_t)p * ((size_t)OW * OW);

    // ---- zero the two column-halo cells (image border) ----
    if (tid < 2 * SM_ROWS) {
        const int r = tid >> 1;
        s[r][(tid & 1) ? 260 : 3] = 0.f;
    }

    // ---- load 34 x 256 slab: 2176 float4 = 8.5 per thread ----
    {
        int i = tid;
        #pragma unroll
        for (int pass = 0; pass < 9; pass++) {
            if (i < SM_ROWS * 64) {
                const int r = i >> 6;          // smem row
                const int j = i & 63;          // float4 index within row
                const int gr = m0 - 1 + r;
                float4 v = make_float4(0.f, 0.f, 0.f, 0.f);
                if ((unsigned)gr < (unsigned)IH)
                    v = *(const float4*)(xp + (size_t)gr * IW + 4 * j);
                *(float4*)&s[r][4 + 4 * j] = v;
            }
            i += 256;
        }
    }

    // separable coefficients: uniform-address broadcast loads (L2-resident);
    // issued before the barrier so their latency overlaps the slab drain.
    const float g0 = __ldg(kk + 0), g1 = __ldg(kk + 1),
                g2 = __ldg(kk + 2), g3 = __ldg(kk + 3);
    const float inv = 1.0f / g0;
    const float r1 = __ldg(kk + 4)  * inv,
                r2 = __ldg(kk + 8)  * inv,
                r3 = __ldg(kk + 12) * inv;

    __syncthreads();

    const int n  = tid;          // input col
    const int lc = n + 4;        // smem col of n

    // prologue: horizontal factors of rows m0-1 (a) and m0 (b)
    float ahE, ahO, bhE, bhO;
    {
        const float a0 = s[0][lc-1], a1 = s[0][lc], a2 = s[0][lc+1];
        ahE = g1 * a1 + g3 * a0;
        ahO = g2 * a1 + g0 * a2;
        const float b0 = s[1][lc-1], b1 = s[1][lc], b2 = s[1][lc+1];
        bhE = g1 * b1 + g3 * b0;
        bhO = g2 * b1 + g0 * b2;
    }

    float* obase = op + ((size_t)m0 * 2) * OW + 2 * n;

    #pragma unroll
    for (int ry = 0; ry < TILE_Y; ry++) {
        const float c0 = s[2 + ry][lc-1];
        const float c1 = s[2 + ry][lc];
        const float c2 = s[2 + ry][lc+1];
        const float chE = g1 * c1 + g3 * c0;
        const float chO = g2 * c1 + g0 * c2;

        const float eE = r1 * bhE + r3 * ahE;
        const float eO = r1 * bhO + r3 * ahO;
        const float oE = r2 * bhE + chE;          // r0 == 1
        const float oO = r2 * bhO + chO;

        float* row0 = obase + (size_t)(2 * ry) * OW;
        *(float2*)row0        = make_float2(eE, eO);
        *(float2*)(row0 + OW) = make_float2(oE, oO);

        ahE = bhE; ahO = bhO;
        bhE = chE; bhO = chO;
    }
}

extern "C" void kernel_launch(void* const* d_in, const int* in_sizes, int n_in,
                              void* d_out, int out_size)
{
    const float* x = (const float*)d_in[0];
    const float* k = (const float*)d_in[1];

    const int nc = in_sizes[0] / (IH * IW);   // 512 planes

    dim3 grid(IH / TILE_Y, nc);   // (8, 512) = 4096 blocks
    upfirdn2x_kernel<<<grid, 256>>>(x, k, (float*)d_out);
}

// round 16
// speedup vs baseline: 1.0053x; 1.0053x over previous
#include <cuda_runtime.h>
#include <cstddef>

// UpsampleUpFIRDn: x (8,64,256,256) f32 -> out (8,64,512,512) f32, up=2, 4x4 FIR.
// Separable parity-reduced form (verified R1/R3):
//   per input row, window (v0=x[n-1], v1=x[n], v2=x[n+1]):
//     hE = g1*v1 + g3*v0 ; hO = g2*v1 + g0*v2      (g_j = k[0][j])
//   vertical combine rows a=m-1, b=m, c=m+1 (r_i = k[i][0]/k[0][0], r0=1):
//     out[2m  ][2n] = r1*bhE + r3*ahE   out[2m  ][2n+1] = r1*bhO + r3*ahO
//     out[2m+1][2n] = r2*bhE + chE      out[2m+1][2n+1] = r2*bhO + chO
//
// FINAL (frozen). Full-width 34x264 smem slab per block, thread = 1 col x 32
// rolling rows, stride-1 lane mapping (conflict-free LDS), STG.64 write-back
// stores, FIR weights read in-kernel (single graph node).
//
// Closed-form floor, all terms at measured minimums:
//   t = 611 MB (compulsory traffic) / 6.2 TB/s (HBM 4:1-write-mix ceiling;
//       LTS cap ~11 TB/s @NAT is not binding) + ~4 us replay overhead
//     ~= 103 us  == measured median (6 identical-binary samples:
//        102.69/102.88/102.91/103.17/103.74/104.96).
// Rejected by experiment: per-thread register blocking (spills, -42%),
// barrier-free streaming (-11%), STG.128 2-col threads (-4%, LDS bank
// conflicts), __stcs, L2 evict_last/evict_first steering, 256-bit loads,
// tile-shape and occupancy sweeps 35-93% (all within +/-2.3 us noise).

#define IH 256
#define IW 256
#define OW 512

#define TILE_Y 32
#define SM_ROWS 34          // TILE_Y + 2 row halo
#define SM_STRIDE 264       // 4 pad | 256 | 4 pad  (col c <-> global col c-4)

__global__ __launch_bounds__(256)
void upfirdn2x_kernel(const float* __restrict__ x,
                      const float* __restrict__ kk,
                      float* __restrict__ out)
{
    __shared__ float s[SM_ROWS][SM_STRIDE];

    const int tid = threadIdx.x;
    const int m0  = blockIdx.x * TILE_Y;    // input row origin
    const int p   = blockIdx.y;             // plane (N*C)

    const float* xp = x + (size_t)p * (IH * IW);
    float* op = out + (size_t)p * ((size_t)OW * OW);

    // ---- zero the two column-halo cells (image border) ----
    if (tid < 2 * SM_ROWS) {
        const int r = tid >> 1;
        s[r][(tid & 1) ? 260 : 3] = 0.f;
    }

    // ---- load 34 x 256 slab: 2176 float4 = 8.5 per thread ----
    {
        int i = tid;
        #pragma unroll
        for (int pass = 0; pass < 9; pass++) {
            if (i < SM_ROWS * 64) {
                const int r = i >> 6;          // smem row
                const int j = i & 63;          // float4 index within row
                const int gr = m0 - 1 + r;
                float4 v = make_float4(0.f, 0.f, 0.f, 0.f);
                if ((unsigned)gr < (unsigned)IH)
                    v = *(const float4*)(xp + (size_t)gr * IW + 4 * j);
                *(float4*)&s[r][4 + 4 * j] = v;
            }
            i += 256;
        }
    }

    // separable coefficients: uniform-address broadcast loads (L2-resident);
    // issued before the barrier so their latency overlaps the slab drain.
    const float g0 = __ldg(kk + 0), g1 = __ldg(kk + 1),
                g2 = __ldg(kk + 2), g3 = __ldg(kk + 3);
    const float inv = 1.0f / g0;
    const float r1 = __ldg(kk + 4)  * inv,
                r2 = __ldg(kk + 8)  * inv,
                r3 = __ldg(kk + 12) * inv;

    __syncthreads();

    const int n  = tid;          // input col
    const int lc = n + 4;        // smem col of n

    // prologue: horizontal factors of rows m0-1 (a) and m0 (b)
    float ahE, ahO, bhE, bhO;
    {
        const float a0 = s[0][lc-1], a1 = s[0][lc], a2 = s[0][lc+1];
        ahE = g1 * a1 + g3 * a0;
        ahO = g2 * a1 + g0 * a2;
        const float b0 = s[1][lc-1], b1 = s[1][lc], b2 = s[1][lc+1];
        bhE = g1 * b1 + g3 * b0;
        bhO = g2 * b1 + g0 * b2;
    }

    float* obase = op + ((size_t)m0 * 2) * OW + 2 * n;

    #pragma unroll
    for (int ry = 0; ry < TILE_Y; ry++) {
        const float c0 = s[2 + ry][lc-1];
        const float c1 = s[2 + ry][lc];
        const float c2 = s[2 + ry][lc+1];
        const float chE = g1 * c1 + g3 * c0;
        const float chO = g2 * c1 + g0 * c2;

        const float eE = r1 * bhE + r3 * ahE;
        const float eO = r1 * bhO + r3 * ahO;
        const float oE = r2 * bhE + chE;          // r0 == 1
        const float oO = r2 * bhO + chO;

        float* row0 = obase + (size_t)(2 * ry) * OW;
        *(float2*)row0        = make_float2(eE, eO);
        *(float2*)(row0 + OW) = make_float2(oE, oO);

        ahE = bhE; ahO = bhO;
        bhE = chE; bhO = chO;
    }
}

extern "C" void kernel_launch(void* const* d_in, const int* in_sizes, int n_in,
                              void* d_out, int out_size)
{
    const float* x = (const float*)d_in[0];
    const float* k = (const float*)d_in[1];

    const int nc = in_sizes[0] / (IH * IW);   // 512 planes

    dim3 grid(IH / TILE_Y, nc);   // (8, 512) = 4096 blocks
    upfirdn2x_kernel<<<grid, 256>>>(x, k, (float*)d_out);
}

// round 17
// speedup vs baseline: 1.0125x; 1.0072x over previous
#include <cuda_runtime.h>
#include <cstddef>

// UpsampleUpFIRDn: x (8,64,256,256) f32 -> out (8,64,512,512) f32, up=2, 4x4 FIR.
// Separable parity-reduced form (verified R1/R3):
//   per input row, window (v0=x[n-1], v1=x[n], v2=x[n+1]):
//     hE = g1*v1 + g3*v0 ; hO = g2*v1 + g0*v2      (g_j = k[0][j])
//   vertical combine rows a=m-1, b=m, c=m+1 (r_i = k[i][0]/k[0][0], r0=1):
//     out[2m  ][2n] = r1*bhE + r3*ahE   out[2m  ][2n+1] = r1*bhO + r3*ahO
//     out[2m+1][2n] = r2*bhE + chE      out[2m+1][2n+1] = r2*bhO + chO
//
// FINAL (held). Full-width 34x264 smem slab per block, thread = 1 col x 32
// rolling rows, stride-1 lane mapping (conflict-free LDS), STG.64 write-back
// stores, FIR weights read in-kernel (single graph node).
//
// Closed-form floor, all terms independently measured at their minimums:
//   t = 611 MB compulsory traffic / 6.2 TB/s (HBM 4:1-write-mix ceiling;
//       LTS cap ~11 TB/s @NAT not binding) + ~4 us graph-replay constant
//     ~= 103 us == median of 7 identical-binary samples
//        (102.69/102.88/102.91/103.17/103.20/103.74/104.96).
// Rejected by experiment: per-thread register blocking (spills, -42%),
// barrier-free streaming (-11%), STG.128 2-col threads (-4%, LDS bank
// conflicts), __stcs, L2 evict_last/evict_first steering, 256-bit loads,
// tile-shape and occupancy sweeps 35-93% (all within +/-2.3 us noise).

#define IH 256
#define IW 256
#define OW 512

#define TILE_Y 32
#define SM_ROWS 34          // TILE_Y + 2 row halo
#define SM_STRIDE 264       // 4 pad | 256 | 4 pad  (col c <-> global col c-4)

__global__ __launch_bounds__(256)
void upfirdn2x_kernel(const float* __restrict__ x,
                      const float* __restrict__ kk,
                      float* __restrict__ out)
{
    __shared__ float s[SM_ROWS][SM_STRIDE];

    const int tid = threadIdx.x;
    const int m0  = blockIdx.x * TILE_Y;    // input row origin
    const int p   = blockIdx.y;             // plane (N*C)

    const float* xp = x + (size_t)p * (IH * IW);
    float* op = out + (size_t)p * ((size_t)OW * OW);

    // ---- zero the two column-halo cells (image border) ----
    if (tid < 2 * SM_ROWS) {
        const int r = tid >> 1;
        s[r][(tid & 1) ? 260 : 3] = 0.f;
    }

    // ---- load 34 x 256 slab: 2176 float4 = 8.5 per thread ----
    {
        int i = tid;
        #pragma unroll
        for (int pass = 0; pass < 9; pass++) {
            if (i < SM_ROWS * 64) {
                const int r = i >> 6;          // smem row
                const int j = i & 63;          // float4 index within row
                const int gr = m0 - 1 + r;
                float4 v = make_float4(0.f, 0.f, 0.f, 0.f);
                if ((unsigned)gr < (unsigned)IH)
                    v = *(const float4*)(xp + (size_t)gr * IW + 4 * j);
                *(float4*)&s[r][4 + 4 * j] = v;
            }
            i += 256;
        }
    }

    // separable coefficients: uniform-address broadcast loads (L2-resident);
    // issued before the barrier so their latency overlaps the slab drain.
    const float g0 = __ldg(kk + 0), g1 = __ldg(kk + 1),
                g2 = __ldg(kk + 2), g3 = __ldg(kk + 3);
    const float inv = 1.0f / g0;
    const float r1 = __ldg(kk + 4)  * inv,
                r2 = __ldg(kk + 8)  * inv,
                r3 = __ldg(kk + 12) * inv;

    __syncthreads();

    const int n  = tid;          // input col
    const int lc = n + 4;        // smem col of n

    // prologue: horizontal factors of rows m0-1 (a) and m0 (b)
    float ahE, ahO, bhE, bhO;
    {
        const float a0 = s[0][lc-1], a1 = s[0][lc], a2 = s[0][lc+1];
        ahE = g1 * a1 + g3 * a0;
        ahO = g2 * a1 + g0 * a2;
        const float b0 = s[1][lc-1], b1 = s[1][lc], b2 = s[1][lc+1];
        bhE = g1 * b1 + g3 * b0;
        bhO = g2 * b1 + g0 * b2;
    }

    float* obase = op + ((size_t)m0 * 2) * OW + 2 * n;

    #pragma unroll
    for (int ry = 0; ry < TILE_Y; ry++) {
        const float c0 = s[2 + ry][lc-1];
        const float c1 = s[2 + ry][lc];
        const float c2 = s[2 + ry][lc+1];
        const float chE = g1 * c1 + g3 * c0;
        const float chO = g2 * c1 + g0 * c2;

        const float eE = r1 * bhE + r3 * ahE;
        const float eO = r1 * bhO + r3 * ahO;
        const float oE = r2 * bhE + chE;          // r0 == 1
        const float oO = r2 * bhO + chO;

        float* row0 = obase + (size_t)(2 * ry) * OW;
        *(float2*)row0        = make_float2(eE, eO);
        *(float2*)(row0 + OW) = make_float2(oE, oO);

        ahE = bhE; ahO = bhO;
        bhE = chE; bhO = chO;
    }
}

extern "C" void kernel_launch(void* const* d_in, const int* in_sizes, int n_in,
                              void* d_out, int out_size)
{
    const float* x = (const float*)d_in[0];
    const float* k = (const float*)d_in[1];

    const int nc = in_sizes[0] / (IH * IW);   // 512 planes

    dim3 grid(IH / TILE_Y, nc);   // (8, 512) = 4096 blocks
    upfirdn2x_kernel<<<grid, 256>>>(x, k, (float*)d_out);
}